// round 15
// baseline (speedup 1.0000x reference)
#include <cuda_runtime.h>
#include <math.h>

#define KC   32
#define HD   64
#define DOBS 32
#define TT   500
#define NCTA 32
#define NT   256
#define LOG2PI 1.8378770664093454835f

// ---------------- cross-step exchange state (double buffered) ----------------
__device__ float  g_lw[2][KC];
__device__ float  g_mu[2][KC][HD];
__device__ float4 g_P[2][KC][HD * HD / 4];
__device__ unsigned g_cnt = 0;
__device__ volatile unsigned g_gen = 0;

// Software grid barrier: 32 CTAs, all co-resident. Generation-relative (replay-safe).
__device__ __forceinline__ void grid_barrier(unsigned &gen)
{
    __threadfence();
    __syncthreads();
    if (threadIdx.x == 0) {
        unsigned prev = atomicAdd(&g_cnt, 1u);
        if (prev == NCTA - 1u) {
            g_cnt = 0u;
            __threadfence();
            g_gen = gen + 1u;
        } else {
            while (g_gen == gen) { }
        }
    }
    __syncthreads();
    __threadfence();
    gen += 1u;
}

// ---------------- register-tiled shared-memory GEMM ----------------
// O[MR x NC] op= sum_h Aload(r,h) * B[h*bs + c];  Aload = ATR ? A[h*as+r] : A[r*as+h]
// MODE 0: O = acc;  MODE 2: O += acc.
template<int MR, int NC, int KD, int TM, int TN, bool ATR, int MODE>
__device__ __forceinline__ void mmT(const float* __restrict__ A, int as,
                                    const float* __restrict__ B, int bs,
                                    float* __restrict__ O, int os,
                                    int tid)
{
    constexpr int GX = NC / TN;
    constexpr int GY = MR / TM;
    static_assert(GX * GY == NT, "thread grid must be NT");
    const int tx = tid % GX;
    const int ty = tid / GX;

    float acc[TM][TN];
#pragma unroll
    for (int i = 0; i < TM; ++i)
#pragma unroll
        for (int jj = 0; jj < TN; ++jj) acc[i][jj] = 0.f;

#pragma unroll 16
    for (int h = 0; h < KD; ++h) {
        float a[TM];
#pragma unroll
        for (int i = 0; i < TM; ++i)
            a[i] = ATR ? A[h * as + ty * TM + i] : A[(ty * TM + i) * as + h];
        float b[TN];
        if constexpr (TN == 4) {
            float4 v = *reinterpret_cast<const float4*>(&B[h * bs + tx * 4]);
            b[0] = v.x; b[1] = v.y; b[2] = v.z; b[3] = v.w;
        } else {
#pragma unroll
            for (int jj = 0; jj < TN; ++jj) b[jj] = B[h * bs + tx * TN + jj];
        }
#pragma unroll
        for (int i = 0; i < TM; ++i)
#pragma unroll
            for (int jj = 0; jj < TN; ++jj)
                acc[i][jj] = fmaf(a[i], b[jj], acc[i][jj]);
    }

#pragma unroll
    for (int i = 0; i < TM; ++i) {
        int r = ty * TM + i;
#pragma unroll
        for (int jj = 0; jj < TN; ++jj) {
            int c = tx * TN + jj;
            if constexpr (MODE == 2) O[r * os + c] += acc[i][jj];
            else                     O[r * os + c]  = acc[i][jj];
        }
    }
}

// ---------------- obs tail: S, Cholesky, solve, update + fused export ----------------
// Requires sBW cols 0..63 = X = C^T P_pred (and sMu = predicted mu).
__device__ __forceinline__ void obs_tail(const float* __restrict__ y,
    float* sP, float* sC, float* sBW, float* sS,
    float* sR, float* sMu, float* sLd, float* sSc, int tid, int j, int b2)
{
    // P8: v (warp 0) + S = X C  (diag(R) added race-free inside Cholesky)
    if (tid < 32) {
        float s = 0.f;
#pragma unroll 8
        for (int h = 0; h < 64; ++h) s = fmaf(sMu[h], sC[h * 32 + tid], s);
        sBW[tid * 68 + 64] = __ldg(&y[tid]) - s;
    }
    mmT<32, 32, 64, 2, 2, false, 0>(sBW, 68, sC, 32, sS, 33, tid);
    __syncthreads();
    // P9: Cholesky of (S + diag(R)) (warp 0): 4-acc dot, shuffle pivot, rsqrt
    if (tid < 32) {
        int r = tid;
        float pivlog = 0.f;
        for (int c = 0; c < 32; ++c) {
            float s = 0.f;
            if (r >= c) {
                s = sS[r * 33 + c];
                if (r == c) s += sR[r];          // diag(R), race-free
                float s1 = 0.f, s2 = 0.f, s3 = 0.f;
                int t2 = 0;
                for (; t2 + 3 < c; t2 += 4) {
                    s  = fmaf(-sS[r * 33 + t2    ], sS[c * 33 + t2    ], s );
                    s1 = fmaf(-sS[r * 33 + t2 + 1], sS[c * 33 + t2 + 1], s1);
                    s2 = fmaf(-sS[r * 33 + t2 + 2], sS[c * 33 + t2 + 2], s2);
                    s3 = fmaf(-sS[r * 33 + t2 + 3], sS[c * 33 + t2 + 3], s3);
                }
                for (; t2 < c; ++t2)
                    s = fmaf(-sS[r * 33 + t2], sS[c * 33 + t2], s);
                s += (s1 + (s2 + s3));
            }
            float d = __shfl_sync(0xffffffffu, s, c);
            d = fmaxf(d, 1e-8f);
            float linv = rsqrtf(d);
            if (r == c) { pivlog = logf(d); sLd[c] = linv; }
            if (r > c) sS[r * 33 + c] = s * linv;
            __syncwarp();
        }
        float v = pivlog;
#pragma unroll
        for (int o = 16; o; o >>= 1) v += __shfl_xor_sync(0xffffffffu, v, o);
        if (r == 0) sSc[1] = v;        // logdet(S)
    }
    __syncthreads();
    // P10: forward solve, 65 RHS, per-thread column in regs, 4-acc dot
    if (tid < 65) {
        float x[32];
#pragma unroll
        for (int r = 0; r < 32; ++r) {
            float s = sBW[r * 68 + tid];
            float s1 = 0.f, s2 = 0.f, s3 = 0.f;
            int t2 = 0;
#pragma unroll
            for (; t2 + 3 < r; t2 += 4) {
                s  = fmaf(-sS[r * 33 + t2    ], x[t2    ], s );
                s1 = fmaf(-sS[r * 33 + t2 + 1], x[t2 + 1], s1);
                s2 = fmaf(-sS[r * 33 + t2 + 2], x[t2 + 2], s2);
                s3 = fmaf(-sS[r * 33 + t2 + 3], x[t2 + 3], s3);
            }
#pragma unroll
            for (; t2 < r; ++t2)
                s = fmaf(-sS[r * 33 + t2], x[t2], s);
            s += (s1 + (s2 + s3));
            x[r] = s * sLd[r];
        }
#pragma unroll
        for (int r = 0; r < 32; ++r) sBW[r * 68 + tid] = x[r];
    }
    __syncthreads();
    // P11: ll + lw export (warp 0), mu update + export (threads<64),
    //      P -= W^T W with per-block P export (all threads).
    if (tid < 32) {
        float xv = sBW[tid * 68 + 64];
        float v2 = xv * xv;
#pragma unroll
        for (int o = 16; o; o >>= 1) v2 += __shfl_xor_sync(0xffffffffu, v2, o);
        if (tid == 0) {
            float inc = -0.5f * (32.f * LOG2PI + sSc[1] + v2);
            if (!(inc > -1e30f) || !(inc < 1e30f)) inc = -1e30f;
            float nlw = sSc[0] + inc;
            if (!(nlw > -1e30f)) nlw = -1e30f;
            sSc[0] = nlw;
            __stcg(&g_lw[b2][j], nlw);
        }
    }
    if (tid < 64) {
        float s = 0.f;
#pragma unroll 8
        for (int d = 0; d < 32; ++d)
            s = fmaf(sBW[d * 68 + tid], sBW[d * 68 + 64], s);
        float nm = sMu[tid] + s;
        sMu[tid] = nm;
        __stcg(&g_mu[b2][j][tid], nm);
    }
    {
        const int tx = tid & 15, ty = tid >> 4;
        float acc[4][4];
#pragma unroll
        for (int i = 0; i < 4; ++i)
#pragma unroll
            for (int jj = 0; jj < 4; ++jj) acc[i][jj] = 0.f;
#pragma unroll 8
        for (int d = 0; d < 32; ++d) {
            float a[4];
#pragma unroll
            for (int i = 0; i < 4; ++i) a[i] = sBW[d * 68 + ty * 4 + i];
            float4 bv = *reinterpret_cast<const float4*>(&sBW[d * 68 + tx * 4]);
#pragma unroll
            for (int i = 0; i < 4; ++i) {
                acc[i][0] = fmaf(a[i], bv.x, acc[i][0]);
                acc[i][1] = fmaf(a[i], bv.y, acc[i][1]);
                acc[i][2] = fmaf(a[i], bv.z, acc[i][2]);
                acc[i][3] = fmaf(a[i], bv.w, acc[i][3]);
            }
        }
#pragma unroll
        for (int i = 0; i < 4; ++i) {
            int r = ty * 4 + i;
            float4 pv = *reinterpret_cast<const float4*>(&sP[r * 64 + tx * 4]);
            pv.x -= acc[i][0]; pv.y -= acc[i][1];
            pv.z -= acc[i][2]; pv.w -= acc[i][3];
            *reinterpret_cast<float4*>(&sP[r * 64 + tx * 4]) = pv;
            __stcg(&g_P[b2][j][r * 16 + tx], pv);   // P exactly symmetric; export fused
        }
    }
    __syncthreads();
}

// ---------------- persistent kernel: one CTA per mixture component ----------------
__global__ void __launch_bounds__(NT, 1)
slds_kernel(const float* __restrict__ data,
            const float* __restrict__ tlogits,
            const float* __restrict__ tmat,
            const float* __restrict__ ltn,
            const float* __restrict__ obsm,
            const float* __restrict__ lon,
            float* __restrict__ out)
{
    extern __shared__ float sh[];
    float* sAU  = sh;             // 96x64: rows 0..63 = A, rows 64..95 = U = C^T A
    float* sAT  = sh + 6144;      // 64x64 (A^T)
    float* sC   = sh + 10240;     // 64x32
    float* sCQ  = sh + 12288;     // 32x64: CQ[d][h] = C[h][d]*Q[h]
    float* sP   = sh + 14336;     // 64x64
    float* sM   = sh + 18432;     // 64x64
    float* sTV  = sh + 22528;     // 96x64: rows 0..63 = T = A*M, rows 64..95 = V = U*M
    float* sDMT = sh + 28672;     // 32x64
    float* sMUK = sh + 30720;     // 32x64 prefetched g_mu
    float* sBW  = sh + 32768;     // 32x68
    float* sS   = sh + 34944;     // 32x33
    float* sQ   = sh + 36000;     // 64
    float* sR   = sh + 36064;     // 32
    float* sMu  = sh + 36096;     // 64
    float* sMB  = sh + 36160;     // 64
    float* sTL  = sh + 36224;     // 32
    float* sRW  = sh + 36256;     // 32
    float* sSR  = sh + 36288;     // 32
    float* sLd  = sh + 36320;     // 32
    float* sSc  = sh + 36352;     // [0]=lw, [1]=logdet

    const int tid = threadIdx.x;
    const int j = blockIdx.x;
    unsigned gen = g_gen;

    float4* sMf = reinterpret_cast<float4*>(sM);

    // ---- constants into shared, once ----
    const float* Ag = tmat + j * 4096;
    for (int i = tid; i < 4096; i += NT) {
        float v = Ag[i];
        int r = i >> 6, c = i & 63;
        sAU[i] = v;               // A rows 0..63
        sAT[c * 64 + r] = v;
    }
    for (int i = tid; i < 2048; i += NT)
        sC[i] = obsm[i];
    if (tid < 64) sQ[tid] = expf(ltn[tid]);
    if (tid < 32) sR[tid] = expf(lon[tid]);
    if (tid >= 64 && tid < 96) {
        int k = tid - 64;
        float m = -1e30f;
        for (int c = 0; c < 32; ++c) m = fmaxf(m, tlogits[k * 32 + c]);
        float s = 0.f;
        for (int c = 0; c < 32; ++c) s += expf(tlogits[k * 32 + c] - m);
        sTL[k] = tlogits[k * 32 + j] - (m + logf(s));
    }
    if (tid >= 128 && tid < 192) sMu[tid - 128] = 0.f;
    for (int i = tid; i < 4096; i += NT) {
        int r = i >> 6, c = i & 63;
        sP[i] = (r == c) ? 1.f : 0.f;
    }
    __syncthreads();
    // U = C^T A (rows 64..95 of sAU; reads rows 0..63 — disjoint) and CQ
    for (int i = tid; i < 2048; i += NT) {
        int d = i >> 6, g = i & 63;
        float s = 0.f;
#pragma unroll 8
        for (int h = 0; h < 64; ++h)
            s = fmaf(sC[h * 32 + d], sAU[h * 64 + g], s);
        sAU[4096 + i] = s;
    }
    for (int i = tid; i < 2048; i += NT) {
        int d = i >> 6, h = i & 63;
        sCQ[i] = sC[h * 32 + d] * sQ[h];
    }
    // t = 0: P = I exactly, so X = C^T (copy); v computed in obs_tail from mu=0
    for (int i = tid; i < 2048; i += NT) {
        int d = i >> 6, h = i & 63;
        sBW[d * 68 + h] = sC[h * 32 + d];
    }
    if (tid == 0) sSc[0] = sTL[0];
    __syncthreads();

    // t = 0 obs tail (exports into buffer 1 for step 1)
    obs_tail(data, sP, sC, sBW, sS, sR, sMu, sLd, sSc, tid, j, 1);

    for (int t = 1; t < TT; ++t) {
        const int b = t & 1;           // buffer exported at end of step t-1
        const int b2 = (t + 1) & 1;    // buffer to export at end of this step

        grid_barrier(gen);

        // P1: weights (warp 0) || prefetch g_mu -> sMUK (threads 32..255)
        if (tid < 32) {
            float lwk = sTL[tid] + __ldcg(&g_lw[b][tid]);
            float m = lwk;
#pragma unroll
            for (int o = 16; o; o >>= 1) m = fmaxf(m, __shfl_xor_sync(0xffffffffu, m, o));
            if (!(m > -9e29f)) {
                sRW[tid] = 1.f / 32.f;
                sSR[tid] = 0.1767766953f;
                if (tid == 0) sSc[0] = -1e30f;
            } else {
                float p = expf(lwk - m);
                float s = p;
#pragma unroll
                for (int o = 16; o; o >>= 1) s += __shfl_xor_sync(0xffffffffu, s, o);
                float rk = p / s;
                sRW[tid] = rk;
                sSR[tid] = sqrtf(rk);
                if (tid == 0) sSc[0] = m + logf(s);
            }
        } else {
            const float4* gm4 = reinterpret_cast<const float4*>(&g_mu[b][0][0]);
            float4* sm4 = reinterpret_cast<float4*>(sMUK);
#pragma unroll
            for (int q = 0; q < 3; ++q) {
                int idx = (tid - 32) + 224 * q;
                if (idx < 512) sm4[idx] = __ldcg(&gm4[idx]);
            }
        }
        __syncthreads();

        // P2: threads 0..63: mu_bar[h] then DMT column h (own-column only; no race)
        //     threads 64..255: M = sum_k r_k P_k (L2 float4 accumulation)
        if (tid < 64) {
            float s = 0.f;
#pragma unroll 8
            for (int k = 0; k < 32; ++k)
                s = fmaf(sRW[k], sMUK[k * 64 + tid], s);
            sMB[tid] = s;
#pragma unroll 8
            for (int k = 0; k < 32; ++k)
                sDMT[k * 64 + tid] = sSR[k] * (sMUK[k * 64 + tid] - s);
        } else {
            const int base = tid - 64;   // 0..191
            float4 acc[5];
#pragma unroll
            for (int q = 0; q < 5; ++q) acc[q] = make_float4(0.f, 0.f, 0.f, 0.f);
            float4 acc5 = make_float4(0.f, 0.f, 0.f, 0.f);
            const bool has6 = (base < 64);
            for (int k = 0; k < 32; ++k) {
                float rk = sRW[k];
                const float4* src = g_P[b][k];
#pragma unroll
                for (int q = 0; q < 5; ++q) {
                    float4 v = __ldcg(&src[base + 192 * q]);
                    acc[q].x = fmaf(rk, v.x, acc[q].x);
                    acc[q].y = fmaf(rk, v.y, acc[q].y);
                    acc[q].z = fmaf(rk, v.z, acc[q].z);
                    acc[q].w = fmaf(rk, v.w, acc[q].w);
                }
                if (has6) {
                    float4 v = __ldcg(&src[base + 960]);
                    acc5.x = fmaf(rk, v.x, acc5.x);
                    acc5.y = fmaf(rk, v.y, acc5.y);
                    acc5.z = fmaf(rk, v.z, acc5.z);
                    acc5.w = fmaf(rk, v.w, acc5.w);
                }
            }
#pragma unroll
            for (int q = 0; q < 5; ++q) sMf[base + 192 * q] = acc[q];
            if (has6) sMf[base + 960] = acc5;
        }
        __syncthreads();

        // P4: M += DMT^T DMT
        mmT<64, 64, 32, 4, 4, true, 2>(sDMT, 64, sDMT, 64, sM, 64, tid);
        __syncthreads();

        // P5: mu = A mu_bar (threads<64) + stacked [T;V] = [A;U] * M (all threads)
        if (tid < 64) {
            float s = 0.f;
#pragma unroll 8
            for (int g = 0; g < 64; ++g) s = fmaf(sAU[tid * 64 + g], sMB[g], s);
            sMu[tid] = s;
        }
        mmT<96, 64, 64, 6, 4, false, 0>(sAU, 64, sM, 64, sTV, 64, tid);
        __syncthreads();

        // P6: threads 0..127: P = T A^T + diag(Q) (triangle + mirror, exact symmetry)
        //     threads 128..255: X = V A^T + CQ -> sBW cols 0..63
        if (tid < 120) {
            // off-diagonal lower block (br > bc)
            int q = tid;
            int br = 1;
            while ((br * (br + 1)) / 2 <= q) ++br;
            int bc = q - (br * (br - 1)) / 2;

            float acc[4][4];
#pragma unroll
            for (int i = 0; i < 4; ++i)
#pragma unroll
                for (int jj = 0; jj < 4; ++jj) acc[i][jj] = 0.f;
#pragma unroll 16
            for (int h = 0; h < 64; ++h) {
                float a[4];
#pragma unroll
                for (int i = 0; i < 4; ++i) a[i] = sTV[(br * 4 + i) * 64 + h];
                float4 bv = *reinterpret_cast<const float4*>(&sAT[h * 64 + bc * 4]);
#pragma unroll
                for (int i = 0; i < 4; ++i) {
                    acc[i][0] = fmaf(a[i], bv.x, acc[i][0]);
                    acc[i][1] = fmaf(a[i], bv.y, acc[i][1]);
                    acc[i][2] = fmaf(a[i], bv.z, acc[i][2]);
                    acc[i][3] = fmaf(a[i], bv.w, acc[i][3]);
                }
            }
#pragma unroll
            for (int i = 0; i < 4; ++i) {
                int r = br * 4 + i;
                float4 w = make_float4(acc[i][0], acc[i][1], acc[i][2], acc[i][3]);
                *reinterpret_cast<float4*>(&sP[r * 64 + bc * 4]) = w;
#pragma unroll
                for (int jj = 0; jj < 4; ++jj)
                    sP[(bc * 4 + jj) * 64 + r] = acc[i][jj];
            }
        } else if (tid < 128) {
            // two diagonal blocks per thread
#pragma unroll
            for (int bb = 0; bb < 2; ++bb) {
                int bd = 2 * (tid - 120) + bb;
                float acc[4][4];
#pragma unroll
                for (int i = 0; i < 4; ++i)
#pragma unroll
                    for (int jj = 0; jj < 4; ++jj) acc[i][jj] = 0.f;
#pragma unroll 16
                for (int h = 0; h < 64; ++h) {
                    float a[4];
#pragma unroll
                    for (int i = 0; i < 4; ++i) a[i] = sTV[(bd * 4 + i) * 64 + h];
                    float4 bv = *reinterpret_cast<const float4*>(&sAT[h * 64 + bd * 4]);
#pragma unroll
                    for (int i = 0; i < 4; ++i) {
                        acc[i][0] = fmaf(a[i], bv.x, acc[i][0]);
                        acc[i][1] = fmaf(a[i], bv.y, acc[i][1]);
                        acc[i][2] = fmaf(a[i], bv.z, acc[i][2]);
                        acc[i][3] = fmaf(a[i], bv.w, acc[i][3]);
                    }
                }
#pragma unroll
                for (int i = 0; i < 4; ++i) {
#pragma unroll
                    for (int jj = 0; jj <= i; ++jj) {
                        int r = bd * 4 + i, c = bd * 4 + jj;
                        float v = acc[i][jj];
                        if (r == c) v += sQ[r];
                        sP[r * 64 + c] = v;
                        sP[c * 64 + r] = v;
                    }
                }
            }
        } else {
            // X = V A^T + CQ : 2 rows x 8 cols per thread
            int q = tid - 128;
            int ty = q >> 3, tx = q & 7;
            float acc[2][8];
#pragma unroll
            for (int i = 0; i < 2; ++i)
#pragma unroll
                for (int jj = 0; jj < 8; ++jj) acc[i][jj] = 0.f;
#pragma unroll 16
            for (int g = 0; g < 64; ++g) {
                float a0 = sTV[4096 + (ty * 2) * 64 + g];
                float a1 = sTV[4096 + (ty * 2 + 1) * 64 + g];
                float4 b0 = *reinterpret_cast<const float4*>(&sAT[g * 64 + tx * 8]);
                float4 b1 = *reinterpret_cast<const float4*>(&sAT[g * 64 + tx * 8 + 4]);
                acc[0][0] = fmaf(a0, b0.x, acc[0][0]); acc[0][1] = fmaf(a0, b0.y, acc[0][1]);
                acc[0][2] = fmaf(a0, b0.z, acc[0][2]); acc[0][3] = fmaf(a0, b0.w, acc[0][3]);
                acc[0][4] = fmaf(a0, b1.x, acc[0][4]); acc[0][5] = fmaf(a0, b1.y, acc[0][5]);
                acc[0][6] = fmaf(a0, b1.z, acc[0][6]); acc[0][7] = fmaf(a0, b1.w, acc[0][7]);
                acc[1][0] = fmaf(a1, b0.x, acc[1][0]); acc[1][1] = fmaf(a1, b0.y, acc[1][1]);
                acc[1][2] = fmaf(a1, b0.z, acc[1][2]); acc[1][3] = fmaf(a1, b0.w, acc[1][3]);
                acc[1][4] = fmaf(a1, b1.x, acc[1][4]); acc[1][5] = fmaf(a1, b1.y, acc[1][5]);
                acc[1][6] = fmaf(a1, b1.z, acc[1][6]); acc[1][7] = fmaf(a1, b1.w, acc[1][7]);
            }
#pragma unroll
            for (int i = 0; i < 2; ++i) {
                int d = ty * 2 + i;
#pragma unroll
                for (int jj = 0; jj < 8; ++jj)
                    sBW[d * 68 + tx * 8 + jj] = acc[i][jj] + sCQ[d * 64 + tx * 8 + jj];
            }
        }
        __syncthreads();

        // P8..P11: obs tail (S, Cholesky, solve, update) + fused export into b2
        obs_tail(data + t * 32, sP, sC, sBW, sS, sR, sMu, sLd, sSc, tid, j, b2);
    }

    // final lw exported to buffer (TT)&1 == 0 at t = TT-1
    grid_barrier(gen);
    if (j == 0 && tid < 32) {
        float lwk = __ldcg(&g_lw[0][tid]);
        float m = lwk;
#pragma unroll
        for (int o = 16; o; o >>= 1) m = fmaxf(m, __shfl_xor_sync(0xffffffffu, m, o));
        float s = expf(lwk - m);
#pragma unroll
        for (int o = 16; o; o >>= 1) s += __shfl_xor_sync(0xffffffffu, s, o);
        if (tid == 0) out[0] = m + logf(s);
    }
}

extern "C" void kernel_launch(void* const* d_in, const int* in_sizes, int n_in,
                              void* d_out, int out_size)
{
    const float *data = nullptr, *tlogits = nullptr, *tmat = nullptr;
    const float *ltn = nullptr, *obsm = nullptr, *lon = nullptr;
    for (int i = 0; i < n_in; ++i) {
        switch (in_sizes[i]) {
            case TT * DOBS:        data    = (const float*)d_in[i]; break;
            case KC * KC:          tlogits = (const float*)d_in[i]; break;
            case KC * HD * HD:     tmat    = (const float*)d_in[i]; break;
            case HD:               ltn     = (const float*)d_in[i]; break;
            case HD * DOBS:        obsm    = (const float*)d_in[i]; break;
            case DOBS:             lon     = (const float*)d_in[i]; break;
        }
    }
    float* out = (float*)d_out;

    const int smem_bytes = 36360 * 4;   // ~145.4 KB dynamic shared
    cudaFuncSetAttribute(slds_kernel,
                         cudaFuncAttributeMaxDynamicSharedMemorySize, smem_bytes);
    slds_kernel<<<NCTA, NT, smem_bytes>>>(data, tlogits, tmat, ltn, obsm, lon, out);
}

// round 16
// speedup vs baseline: 1.1019x; 1.1019x over previous
#include <cuda_runtime.h>
#include <math.h>

#define KC   32
#define HD   64
#define DOBS 32
#define TT   500
#define NCTA 32
#define NT   256
#define LOG2PI 1.8378770664093454835f

// ---------------- cross-step exchange state (double buffered) ----------------
__device__ float  g_lw[2][KC];
__device__ float  g_mu[2][KC][HD];
__device__ float4 g_P[2][KC][HD * HD / 4];
__device__ unsigned g_cnt = 0;
__device__ volatile unsigned g_gen = 0;

// Software grid barrier: 32 CTAs, all co-resident. Generation-relative (replay-safe).
__device__ __forceinline__ void grid_barrier(unsigned &gen)
{
    __threadfence();
    __syncthreads();
    if (threadIdx.x == 0) {
        unsigned prev = atomicAdd(&g_cnt, 1u);
        if (prev == NCTA - 1u) {
            g_cnt = 0u;
            __threadfence();
            g_gen = gen + 1u;
        } else {
            while (g_gen == gen) { }
        }
    }
    __syncthreads();
    __threadfence();
    gen += 1u;
}

// ---------------- register-tiled shared-memory GEMM (R7 form) ----------------
// O[MR x NC] op= sum_h Aload(r,h) * B[h*bs + c];  Aload = ATR ? A[h*as+r] : A[r*as+h]
// MODE 0: O = acc;  MODE 2: O += acc.
template<int MR, int NC, int KD, int TM, int TN, bool ATR, int MODE>
__device__ __forceinline__ void mmT(const float* __restrict__ A, int as,
                                    const float* __restrict__ B, int bs,
                                    float* __restrict__ O, int os,
                                    int tid)
{
    constexpr int GX = NC / TN;
    constexpr int GY = MR / TM;
    static_assert(GX * GY == NT, "thread grid must be NT");
    const int tx = tid % GX;
    const int ty = tid / GX;

    float acc[TM][TN];
#pragma unroll
    for (int i = 0; i < TM; ++i)
#pragma unroll
        for (int jj = 0; jj < TN; ++jj) acc[i][jj] = 0.f;

#pragma unroll 16
    for (int h = 0; h < KD; ++h) {
        float a[TM];
#pragma unroll
        for (int i = 0; i < TM; ++i)
            a[i] = ATR ? A[h * as + ty * TM + i] : A[(ty * TM + i) * as + h];
        float b[TN];
        if constexpr (TN == 4) {
            float4 v = *reinterpret_cast<const float4*>(&B[h * bs + tx * 4]);
            b[0] = v.x; b[1] = v.y; b[2] = v.z; b[3] = v.w;
        } else {
#pragma unroll
            for (int jj = 0; jj < TN; ++jj) b[jj] = B[h * bs + tx * TN + jj];
        }
#pragma unroll
        for (int i = 0; i < TM; ++i)
#pragma unroll
            for (int jj = 0; jj < TN; ++jj)
                acc[i][jj] = fmaf(a[i], b[jj], acc[i][jj]);
    }

#pragma unroll
    for (int i = 0; i < TM; ++i) {
        int r = ty * TM + i;
#pragma unroll
        for (int jj = 0; jj < TN; ++jj) {
            int c = tx * TN + jj;
            if constexpr (MODE == 2) O[r * os + c] += acc[i][jj];
            else                     O[r * os + c]  = acc[i][jj];
        }
    }
}

// ---------------- observation update + fused export ----------------
// sBW: 32 x 68 — cols 0..63: C^T P then W; col 64: v then w_v.
__device__ __forceinline__ void obs_update(const float* __restrict__ y,
    float* sP, float* sC, float* sCT, float* sBW, float* sS,
    float* sR, float* sMu, float* sLd, float* sSc, int tid, int j, int b2)
{
    // P7: innovation v (warp 0 work) + X = C^T P
    if (tid < 32) {
        float s = 0.f;
#pragma unroll 8
        for (int h = 0; h < 64; ++h) s = fmaf(sMu[h], sC[h * 32 + tid], s);
        sBW[tid * 68 + 64] = __ldg(&y[tid]) - s;
    }
    mmT<32, 64, 64, 2, 4, false, 0>(sCT, 64, sP, 64, sBW, 68, tid);
    __syncthreads();
    // P8: S = X C   (diag(R) is added race-free inside the Cholesky below)
    mmT<32, 32, 64, 2, 2, false, 0>(sBW, 68, sC, 32, sS, 33, tid);
    __syncthreads();
    // P9: Cholesky of (S + diag(R)) (warp 0): 4-acc dot, shuffle pivot, rsqrt.
    if (tid < 32) {
        int r = tid;
        float pivlog = 0.f;
        for (int c = 0; c < 32; ++c) {
            float s = 0.f;
            if (r >= c) {
                s = sS[r * 33 + c];
                if (r == c) s += sR[r];          // diag(R), race-free
                float s1 = 0.f, s2 = 0.f, s3 = 0.f;
                int t2 = 0;
                for (; t2 + 3 < c; t2 += 4) {
                    s  = fmaf(-sS[r * 33 + t2    ], sS[c * 33 + t2    ], s );
                    s1 = fmaf(-sS[r * 33 + t2 + 1], sS[c * 33 + t2 + 1], s1);
                    s2 = fmaf(-sS[r * 33 + t2 + 2], sS[c * 33 + t2 + 2], s2);
                    s3 = fmaf(-sS[r * 33 + t2 + 3], sS[c * 33 + t2 + 3], s3);
                }
                for (; t2 < c; ++t2)
                    s = fmaf(-sS[r * 33 + t2], sS[c * 33 + t2], s);
                s += (s1 + (s2 + s3));
            }
            float d = __shfl_sync(0xffffffffu, s, c);
            d = fmaxf(d, 1e-8f);
            float linv = rsqrtf(d);
            if (r == c) { pivlog = logf(d); sLd[c] = linv; }
            if (r > c) sS[r * 33 + c] = s * linv;
            __syncwarp();
        }
        float v = pivlog;
#pragma unroll
        for (int o = 16; o; o >>= 1) v += __shfl_xor_sync(0xffffffffu, v, o);
        if (r == 0) sSc[1] = v;        // logdet(S)
    }
    __syncthreads();
    // P10: forward solve, 65 RHS, per-thread column in regs, 4-acc dot
    if (tid < 65) {
        float x[32];
#pragma unroll
        for (int r = 0; r < 32; ++r) {
            float s = sBW[r * 68 + tid];
            float s1 = 0.f, s2 = 0.f, s3 = 0.f;
            int t2 = 0;
#pragma unroll
            for (; t2 + 3 < r; t2 += 4) {
                s  = fmaf(-sS[r * 33 + t2    ], x[t2    ], s );
                s1 = fmaf(-sS[r * 33 + t2 + 1], x[t2 + 1], s1);
                s2 = fmaf(-sS[r * 33 + t2 + 2], x[t2 + 2], s2);
                s3 = fmaf(-sS[r * 33 + t2 + 3], x[t2 + 3], s3);
            }
#pragma unroll
            for (; t2 < r; ++t2)
                s = fmaf(-sS[r * 33 + t2], x[t2], s);
            s += (s1 + (s2 + s3));
            x[r] = s * sLd[r];
        }
#pragma unroll
        for (int r = 0; r < 32; ++r) sBW[r * 68 + tid] = x[r];
    }
    __syncthreads();
    // P11: ll + lw export (warp 0), mu update + export (threads<64),
    //      P -= W^T W with per-block P export (all threads).
    if (tid < 32) {
        float xv = sBW[tid * 68 + 64];
        float v2 = xv * xv;
#pragma unroll
        for (int o = 16; o; o >>= 1) v2 += __shfl_xor_sync(0xffffffffu, v2, o);
        if (tid == 0) {
            float inc = -0.5f * (32.f * LOG2PI + sSc[1] + v2);
            if (!(inc > -1e30f) || !(inc < 1e30f)) inc = -1e30f;
            float nlw = sSc[0] + inc;
            if (!(nlw > -1e30f)) nlw = -1e30f;
            sSc[0] = nlw;
            __stcg(&g_lw[b2][j], nlw);
        }
    }
    if (tid < 64) {
        float s = 0.f;
#pragma unroll 8
        for (int d = 0; d < 32; ++d)
            s = fmaf(sBW[d * 68 + tid], sBW[d * 68 + 64], s);
        float nm = sMu[tid] + s;
        sMu[tid] = nm;
        __stcg(&g_mu[b2][j][tid], nm);
    }
    {
        const int tx = tid & 15, ty = tid >> 4;
        float acc[4][4];
#pragma unroll
        for (int i = 0; i < 4; ++i)
#pragma unroll
            for (int jj = 0; jj < 4; ++jj) acc[i][jj] = 0.f;
#pragma unroll 8
        for (int d = 0; d < 32; ++d) {
            float a[4];
#pragma unroll
            for (int i = 0; i < 4; ++i) a[i] = sBW[d * 68 + ty * 4 + i];
            float4 bv = *reinterpret_cast<const float4*>(&sBW[d * 68 + tx * 4]);
#pragma unroll
            for (int i = 0; i < 4; ++i) {
                acc[i][0] = fmaf(a[i], bv.x, acc[i][0]);
                acc[i][1] = fmaf(a[i], bv.y, acc[i][1]);
                acc[i][2] = fmaf(a[i], bv.z, acc[i][2]);
                acc[i][3] = fmaf(a[i], bv.w, acc[i][3]);
            }
        }
#pragma unroll
        for (int i = 0; i < 4; ++i) {
            int r = ty * 4 + i;
            float4 pv = *reinterpret_cast<const float4*>(&sP[r * 64 + tx * 4]);
            pv.x -= acc[i][0]; pv.y -= acc[i][1];
            pv.z -= acc[i][2]; pv.w -= acc[i][3];
            *reinterpret_cast<float4*>(&sP[r * 64 + tx * 4]) = pv;
            __stcg(&g_P[b2][j][r * 16 + tx], pv);   // P exactly symmetric; export fused
        }
    }
    __syncthreads();
}

// ---------------- persistent kernel: one CTA per mixture component ----------------
__global__ void __launch_bounds__(NT, 1)
slds_kernel(const float* __restrict__ data,
            const float* __restrict__ tlogits,
            const float* __restrict__ tmat,
            const float* __restrict__ ltn,
            const float* __restrict__ obsm,
            const float* __restrict__ lon,
            float* __restrict__ out)
{
    extern __shared__ float sh[];
    float* sA   = sh;             // 64x64
    float* sAT  = sh + 4096;      // 64x64 (A^T)
    float* sC   = sh + 8192;      // 64x32
    float* sCT  = sh + 10240;     // 32x64
    float* sP   = sh + 12288;     // 64x64
    float* sM   = sh + 16384;     // 64x64
    float* sT   = sh + 20480;     // 64x64
    float* sDMT = sh + 24576;     // 32x64
    float* sMUK = sh + 26624;     // 32x64 prefetched g_mu
    float* sBW  = sh + 28672;     // 32x68
    float* sS   = sh + 30848;     // 32x33
    float* sQ   = sh + 31904;     // 64
    float* sR   = sh + 31968;     // 32
    float* sMu  = sh + 32000;     // 64
    float* sMB  = sh + 32064;     // 64
    float* sTL  = sh + 32128;     // 32
    float* sRW  = sh + 32160;     // 32
    float* sSR  = sh + 32192;     // 32
    float* sLd  = sh + 32224;     // 32
    float* sSc  = sh + 32256;     // [0]=lw, [1]=logdet

    const int tid = threadIdx.x;
    const int j = blockIdx.x;
    unsigned gen = g_gen;

    float4* sMf = reinterpret_cast<float4*>(sM);

    // ---- constants into shared, once ----
    const float* Ag = tmat + j * 4096;
    for (int i = tid; i < 4096; i += NT) {
        float v = Ag[i];
        int r = i >> 6, c = i & 63;
        sA[i] = v;
        sAT[c * 64 + r] = v;
    }
    for (int i = tid; i < 2048; i += NT) {
        float v = obsm[i];
        int h = i >> 5, d = i & 31;
        sC[i] = v;
        sCT[d * 64 + h] = v;
    }
    if (tid < 64) sQ[tid] = expf(ltn[tid]);
    if (tid < 32) sR[tid] = expf(lon[tid]);
    if (tid >= 64 && tid < 96) {
        int k = tid - 64;
        float m = -1e30f;
        for (int c = 0; c < 32; ++c) m = fmaxf(m, tlogits[k * 32 + c]);
        float s = 0.f;
        for (int c = 0; c < 32; ++c) s += expf(tlogits[k * 32 + c] - m);
        sTL[k] = tlogits[k * 32 + j] - (m + logf(s));
    }
    if (tid >= 128 && tid < 192) sMu[tid - 128] = 0.f;
    for (int i = tid; i < 4096; i += NT) {
        int r = i >> 6, c = i & 63;
        sP[i] = (r == c) ? 1.f : 0.f;
    }
    __syncthreads();
    if (tid == 0) sSc[0] = sTL[0];
    __syncthreads();

    // t = 0 observation update (exports into buffer 1 for step 1)
    obs_update(data, sP, sC, sCT, sBW, sS, sR, sMu, sLd, sSc, tid, j, 1);

    for (int t = 1; t < TT; ++t) {
        const int b = t & 1;           // buffer exported at end of step t-1
        const int b2 = (t + 1) & 1;    // buffer to export at end of this step

        grid_barrier(gen);

        // P1: weights (warp 0) || prefetch g_mu -> sMUK (threads 32..255)
        if (tid < 32) {
            float lwk = sTL[tid] + __ldcg(&g_lw[b][tid]);
            float m = lwk;
#pragma unroll
            for (int o = 16; o; o >>= 1) m = fmaxf(m, __shfl_xor_sync(0xffffffffu, m, o));
            if (!(m > -9e29f)) {
                sRW[tid] = 1.f / 32.f;
                sSR[tid] = 0.1767766953f;
                if (tid == 0) sSc[0] = -1e30f;
            } else {
                float p = expf(lwk - m);
                float s = p;
#pragma unroll
                for (int o = 16; o; o >>= 1) s += __shfl_xor_sync(0xffffffffu, s, o);
                float rk = p / s;
                sRW[tid] = rk;
                sSR[tid] = sqrtf(rk);
                if (tid == 0) sSc[0] = m + logf(s);
            }
        } else {
            const float4* gm4 = reinterpret_cast<const float4*>(&g_mu[b][0][0]);
            float4* sm4 = reinterpret_cast<float4*>(sMUK);
#pragma unroll
            for (int q = 0; q < 3; ++q) {
                int idx = (tid - 32) + 224 * q;
                if (idx < 512) sm4[idx] = __ldcg(&gm4[idx]);
            }
        }
        __syncthreads();

        // P2 (merged with old P3): threads 0..63: mu_bar[h], then DMT column h
        //     (own column only — no cross-thread hazard; hidden under M-accum).
        //     threads 64..255: M = sum_k r_k P_k (512 KB L2 float4 accumulation).
        if (tid < 64) {
            float s = 0.f;
#pragma unroll 8
            for (int k = 0; k < 32; ++k)
                s = fmaf(sRW[k], sMUK[k * 64 + tid], s);
            sMB[tid] = s;
#pragma unroll 8
            for (int k = 0; k < 32; ++k)
                sDMT[k * 64 + tid] = sSR[k] * (sMUK[k * 64 + tid] - s);
        } else {
            const int base = tid - 64;   // 0..191
            float4 acc[5];
#pragma unroll
            for (int q = 0; q < 5; ++q) acc[q] = make_float4(0.f, 0.f, 0.f, 0.f);
            float4 acc5 = make_float4(0.f, 0.f, 0.f, 0.f);
            const bool has6 = (base < 64);
            for (int k = 0; k < 32; ++k) {
                float rk = sRW[k];
                const float4* src = g_P[b][k];
#pragma unroll
                for (int q = 0; q < 5; ++q) {
                    float4 v = __ldcg(&src[base + 192 * q]);
                    acc[q].x = fmaf(rk, v.x, acc[q].x);
                    acc[q].y = fmaf(rk, v.y, acc[q].y);
                    acc[q].z = fmaf(rk, v.z, acc[q].z);
                    acc[q].w = fmaf(rk, v.w, acc[q].w);
                }
                if (has6) {
                    float4 v = __ldcg(&src[base + 960]);
                    acc5.x = fmaf(rk, v.x, acc5.x);
                    acc5.y = fmaf(rk, v.y, acc5.y);
                    acc5.z = fmaf(rk, v.z, acc5.z);
                    acc5.w = fmaf(rk, v.w, acc5.w);
                }
            }
#pragma unroll
            for (int q = 0; q < 5; ++q) sMf[base + 192 * q] = acc[q];
            if (has6) sMf[base + 960] = acc5;
        }
        __syncthreads();

        // P4: M += DMT^T DMT
        mmT<64, 64, 32, 4, 4, true, 2>(sDMT, 64, sDMT, 64, sM, 64, tid);
        __syncthreads();

        // P5: mu = A mu_bar (threads<64), then T = A M (all threads, same phase)
        if (tid < 64) {
            float s = 0.f;
#pragma unroll 8
            for (int g = 0; g < 64; ++g) s = fmaf(sA[tid * 64 + g], sMB[g], s);
            sMu[tid] = s;
        }
        mmT<64, 64, 64, 4, 4, false, 0>(sA, 64, sM, 64, sT, 64, tid);
        __syncthreads();

        // P6: P = T A^T + diag(Q), lower-triangle blocks + mirror (exactly symmetric)
        if (tid < 136) {
            int br = (int)((sqrtf(8.f * tid + 1.f) - 1.f) * 0.5f);
            while ((br + 1) * (br + 2) / 2 <= tid) ++br;
            while (br * (br + 1) / 2 > tid) --br;
            int bc = tid - br * (br + 1) / 2;

            float acc[4][4];
#pragma unroll
            for (int i = 0; i < 4; ++i)
#pragma unroll
                for (int jj = 0; jj < 4; ++jj) acc[i][jj] = 0.f;
#pragma unroll 16
            for (int h = 0; h < 64; ++h) {
                float a[4];
#pragma unroll
                for (int i = 0; i < 4; ++i) a[i] = sT[(br * 4 + i) * 64 + h];
                float4 bv = *reinterpret_cast<const float4*>(&sAT[h * 64 + bc * 4]);
#pragma unroll
                for (int i = 0; i < 4; ++i) {
                    acc[i][0] = fmaf(a[i], bv.x, acc[i][0]);
                    acc[i][1] = fmaf(a[i], bv.y, acc[i][1]);
                    acc[i][2] = fmaf(a[i], bv.z, acc[i][2]);
                    acc[i][3] = fmaf(a[i], bv.w, acc[i][3]);
                }
            }
            if (br > bc) {
#pragma unroll
                for (int i = 0; i < 4; ++i) {
                    int r = br * 4 + i;
                    float4 w = make_float4(acc[i][0], acc[i][1], acc[i][2], acc[i][3]);
                    *reinterpret_cast<float4*>(&sP[r * 64 + bc * 4]) = w;
#pragma unroll
                    for (int jj = 0; jj < 4; ++jj)
                        sP[(bc * 4 + jj) * 64 + r] = acc[i][jj];
                }
            } else {  // diagonal block: use lower part only, mirror within block
#pragma unroll
                for (int i = 0; i < 4; ++i) {
#pragma unroll
                    for (int jj = 0; jj <= i; ++jj) {
                        int r = br * 4 + i, c = bc * 4 + jj;
                        float v = acc[i][jj];
                        if (r == c) v += sQ[r];
                        sP[r * 64 + c] = v;
                        sP[c * 64 + r] = v;
                    }
                }
            }
        }
        __syncthreads();

        // P7..P11: observation update + fused export into buffer b2
        obs_update(data + t * 32, sP, sC, sCT, sBW, sS, sR, sMu, sLd, sSc, tid, j, b2);
    }

    // final lw exported to buffer (TT)&1 == 0 at t = TT-1
    grid_barrier(gen);
    if (j == 0 && tid < 32) {
        float lwk = __ldcg(&g_lw[0][tid]);
        float m = lwk;
#pragma unroll
        for (int o = 16; o; o >>= 1) m = fmaxf(m, __shfl_xor_sync(0xffffffffu, m, o));
        float s = expf(lwk - m);
#pragma unroll
        for (int o = 16; o; o >>= 1) s += __shfl_xor_sync(0xffffffffu, s, o);
        if (tid == 0) out[0] = m + logf(s);
    }
}

extern "C" void kernel_launch(void* const* d_in, const int* in_sizes, int n_in,
                              void* d_out, int out_size)
{
    const float *data = nullptr, *tlogits = nullptr, *tmat = nullptr;
    const float *ltn = nullptr, *obsm = nullptr, *lon = nullptr;
    for (int i = 0; i < n_in; ++i) {
        switch (in_sizes[i]) {
            case TT * DOBS:        data    = (const float*)d_in[i]; break;
            case KC * KC:          tlogits = (const float*)d_in[i]; break;
            case KC * HD * HD:     tmat    = (const float*)d_in[i]; break;
            case HD:               ltn     = (const float*)d_in[i]; break;
            case HD * DOBS:        obsm    = (const float*)d_in[i]; break;
            case DOBS:             lon     = (const float*)d_in[i]; break;
        }
    }
    float* out = (float*)d_out;

    const int smem_bytes = 32264 * 4;   // ~129 KB dynamic shared
    cudaFuncSetAttribute(slds_kernel,
                         cudaFuncAttributeMaxDynamicSharedMemorySize, smem_bytes);
    slds_kernel<<<NCTA, NT, smem_bytes>>>(data, tlogits, tmat, ltn, obsm, lon, out);
}

// round 17
// speedup vs baseline: 1.1047x; 1.0025x over previous
#include <cuda_runtime.h>
#include <math.h>

#define KC   32
#define HD   64
#define DOBS 32
#define TT   500
#define NCTA 32
#define NT   256
#define LOG2PI 1.8378770664093454835f

// ---------------- cross-step exchange state (double buffered) ----------------
// P exchanged as packed lower-triangle of 4x4 blocks: 136 blocks x 4 float4 rows.
__device__ float  g_lw[2][KC];
__device__ float  g_mu[2][KC][HD];
__device__ float4 g_P[2][KC][544];
__device__ unsigned g_cnt = 0;
__device__ volatile unsigned g_gen = 0;

// Software grid barrier: 32 CTAs, all co-resident. Generation-relative (replay-safe).
__device__ __forceinline__ void grid_barrier(unsigned &gen)
{
    __threadfence();
    __syncthreads();
    if (threadIdx.x == 0) {
        unsigned prev = atomicAdd(&g_cnt, 1u);
        if (prev == NCTA - 1u) {
            g_cnt = 0u;
            __threadfence();
            g_gen = gen + 1u;
        } else {
            while (g_gen == gen) { }
        }
    }
    __syncthreads();
    __threadfence();
    gen += 1u;
}

// ---------------- register-tiled shared-memory GEMM (R7 form) ----------------
// O[MR x NC] op= sum_h Aload(r,h) * B[h*bs + c];  Aload = ATR ? A[h*as+r] : A[r*as+h]
// MODE 0: O = acc;  MODE 2: O += acc.
template<int MR, int NC, int KD, int TM, int TN, bool ATR, int MODE>
__device__ __forceinline__ void mmT(const float* __restrict__ A, int as,
                                    const float* __restrict__ B, int bs,
                                    float* __restrict__ O, int os,
                                    int tid)
{
    constexpr int GX = NC / TN;
    constexpr int GY = MR / TM;
    static_assert(GX * GY == NT, "thread grid must be NT");
    const int tx = tid % GX;
    const int ty = tid / GX;

    float acc[TM][TN];
#pragma unroll
    for (int i = 0; i < TM; ++i)
#pragma unroll
        for (int jj = 0; jj < TN; ++jj) acc[i][jj] = 0.f;

#pragma unroll 16
    for (int h = 0; h < KD; ++h) {
        float a[TM];
#pragma unroll
        for (int i = 0; i < TM; ++i)
            a[i] = ATR ? A[h * as + ty * TM + i] : A[(ty * TM + i) * as + h];
        float b[TN];
        if constexpr (TN == 4) {
            float4 v = *reinterpret_cast<const float4*>(&B[h * bs + tx * 4]);
            b[0] = v.x; b[1] = v.y; b[2] = v.z; b[3] = v.w;
        } else {
#pragma unroll
            for (int jj = 0; jj < TN; ++jj) b[jj] = B[h * bs + tx * TN + jj];
        }
#pragma unroll
        for (int i = 0; i < TM; ++i)
#pragma unroll
            for (int jj = 0; jj < TN; ++jj)
                acc[i][jj] = fmaf(a[i], b[jj], acc[i][jj]);
    }

#pragma unroll
    for (int i = 0; i < TM; ++i) {
        int r = ty * TM + i;
#pragma unroll
        for (int jj = 0; jj < TN; ++jj) {
            int c = tx * TN + jj;
            if constexpr (MODE == 2) O[r * os + c] += acc[i][jj];
            else                     O[r * os + c]  = acc[i][jj];
        }
    }
}

// ---------------- observation update + fused triangle export ----------------
// sBW: 32 x 68 — cols 0..63: C^T P then W; col 64: v then w_v.
__device__ __forceinline__ void obs_update(const float* __restrict__ y,
    float* sP, float* sC, float* sCT, float* sBW, float* sS,
    float* sR, float* sMu, float* sLd, float* sSc, int tid, int j, int b2)
{
    // P7: innovation v (warp 0 work) + X = C^T P
    if (tid < 32) {
        float s = 0.f;
#pragma unroll 8
        for (int h = 0; h < 64; ++h) s = fmaf(sMu[h], sC[h * 32 + tid], s);
        sBW[tid * 68 + 64] = __ldg(&y[tid]) - s;
    }
    mmT<32, 64, 64, 2, 4, false, 0>(sCT, 64, sP, 64, sBW, 68, tid);
    __syncthreads();
    // P8: S = X C   (diag(R) is added race-free inside the Cholesky below)
    mmT<32, 32, 64, 2, 2, false, 0>(sBW, 68, sC, 32, sS, 33, tid);
    __syncthreads();
    // P9: Cholesky of (S + diag(R)) (warp 0): 4-acc dot, shuffle pivot, rsqrt.
    if (tid < 32) {
        int r = tid;
        float pivlog = 0.f;
        for (int c = 0; c < 32; ++c) {
            float s = 0.f;
            if (r >= c) {
                s = sS[r * 33 + c];
                if (r == c) s += sR[r];          // diag(R), race-free
                float s1 = 0.f, s2 = 0.f, s3 = 0.f;
                int t2 = 0;
                for (; t2 + 3 < c; t2 += 4) {
                    s  = fmaf(-sS[r * 33 + t2    ], sS[c * 33 + t2    ], s );
                    s1 = fmaf(-sS[r * 33 + t2 + 1], sS[c * 33 + t2 + 1], s1);
                    s2 = fmaf(-sS[r * 33 + t2 + 2], sS[c * 33 + t2 + 2], s2);
                    s3 = fmaf(-sS[r * 33 + t2 + 3], sS[c * 33 + t2 + 3], s3);
                }
                for (; t2 < c; ++t2)
                    s = fmaf(-sS[r * 33 + t2], sS[c * 33 + t2], s);
                s += (s1 + (s2 + s3));
            }
            float d = __shfl_sync(0xffffffffu, s, c);
            d = fmaxf(d, 1e-8f);
            float linv = rsqrtf(d);
            if (r == c) { pivlog = logf(d); sLd[c] = linv; }
            if (r > c) sS[r * 33 + c] = s * linv;
            __syncwarp();
        }
        float v = pivlog;
#pragma unroll
        for (int o = 16; o; o >>= 1) v += __shfl_xor_sync(0xffffffffu, v, o);
        if (r == 0) sSc[1] = v;        // logdet(S)
    }
    __syncthreads();
    // P10: forward solve, 65 RHS, per-thread column in regs, 4-acc dot
    if (tid < 65) {
        float x[32];
#pragma unroll
        for (int r = 0; r < 32; ++r) {
            float s = sBW[r * 68 + tid];
            float s1 = 0.f, s2 = 0.f, s3 = 0.f;
            int t2 = 0;
#pragma unroll
            for (; t2 + 3 < r; t2 += 4) {
                s  = fmaf(-sS[r * 33 + t2    ], x[t2    ], s );
                s1 = fmaf(-sS[r * 33 + t2 + 1], x[t2 + 1], s1);
                s2 = fmaf(-sS[r * 33 + t2 + 2], x[t2 + 2], s2);
                s3 = fmaf(-sS[r * 33 + t2 + 3], x[t2 + 3], s3);
            }
#pragma unroll
            for (; t2 < r; ++t2)
                s = fmaf(-sS[r * 33 + t2], x[t2], s);
            s += (s1 + (s2 + s3));
            x[r] = s * sLd[r];
        }
#pragma unroll
        for (int r = 0; r < 32; ++r) sBW[r * 68 + tid] = x[r];
    }
    __syncthreads();
    // P11: ll + lw export (warp 0), mu update + export (threads<64),
    //      P -= W^T W with per-block lower-triangle P export (ty >= tx only).
    if (tid < 32) {
        float xv = sBW[tid * 68 + 64];
        float v2 = xv * xv;
#pragma unroll
        for (int o = 16; o; o >>= 1) v2 += __shfl_xor_sync(0xffffffffu, v2, o);
        if (tid == 0) {
            float inc = -0.5f * (32.f * LOG2PI + sSc[1] + v2);
            if (!(inc > -1e30f) || !(inc < 1e30f)) inc = -1e30f;
            float nlw = sSc[0] + inc;
            if (!(nlw > -1e30f)) nlw = -1e30f;
            sSc[0] = nlw;
            __stcg(&g_lw[b2][j], nlw);
        }
    }
    if (tid < 64) {
        float s = 0.f;
#pragma unroll 8
        for (int d = 0; d < 32; ++d)
            s = fmaf(sBW[d * 68 + tid], sBW[d * 68 + 64], s);
        float nm = sMu[tid] + s;
        sMu[tid] = nm;
        __stcg(&g_mu[b2][j][tid], nm);
    }
    {
        const int tx = tid & 15, ty = tid >> 4;
        const bool expo = (ty >= tx);
        const int bi = ty * (ty + 1) / 2 + tx;   // packed triangle block index
        float acc[4][4];
#pragma unroll
        for (int i = 0; i < 4; ++i)
#pragma unroll
            for (int jj = 0; jj < 4; ++jj) acc[i][jj] = 0.f;
#pragma unroll 8
        for (int d = 0; d < 32; ++d) {
            float a[4];
#pragma unroll
            for (int i = 0; i < 4; ++i) a[i] = sBW[d * 68 + ty * 4 + i];
            float4 bv = *reinterpret_cast<const float4*>(&sBW[d * 68 + tx * 4]);
#pragma unroll
            for (int i = 0; i < 4; ++i) {
                acc[i][0] = fmaf(a[i], bv.x, acc[i][0]);
                acc[i][1] = fmaf(a[i], bv.y, acc[i][1]);
                acc[i][2] = fmaf(a[i], bv.z, acc[i][2]);
                acc[i][3] = fmaf(a[i], bv.w, acc[i][3]);
            }
        }
#pragma unroll
        for (int i = 0; i < 4; ++i) {
            int r = ty * 4 + i;
            float4 pv = *reinterpret_cast<const float4*>(&sP[r * 64 + tx * 4]);
            pv.x -= acc[i][0]; pv.y -= acc[i][1];
            pv.z -= acc[i][2]; pv.w -= acc[i][3];
            *reinterpret_cast<float4*>(&sP[r * 64 + tx * 4]) = pv;
            if (expo) __stcg(&g_P[b2][j][bi * 4 + i], pv);   // exact symmetry: triangle only
        }
    }
    // no trailing __syncthreads: caller's grid_barrier starts with one
}

// ---------------- persistent kernel: one CTA per mixture component ----------------
__global__ void __launch_bounds__(NT, 1)
slds_kernel(const float* __restrict__ data,
            const float* __restrict__ tlogits,
            const float* __restrict__ tmat,
            const float* __restrict__ ltn,
            const float* __restrict__ obsm,
            const float* __restrict__ lon,
            float* __restrict__ out)
{
    extern __shared__ float sh[];
    float* sA   = sh;             // 64x64
    float* sAT  = sh + 4096;      // 64x64 (A^T)
    float* sC   = sh + 8192;      // 64x32
    float* sCT  = sh + 10240;     // 32x64
    float* sP   = sh + 12288;     // 64x64
    float* sM   = sh + 16384;     // 64x64
    float* sT   = sh + 20480;     // 64x64
    float* sDMT = sh + 24576;     // 32x64
    float* sMUK = sh + 26624;     // 32x64 prefetched g_mu
    float* sBW  = sh + 28672;     // 32x68
    float* sS   = sh + 30848;     // 32x33
    float* sQ   = sh + 31904;     // 64
    float* sR   = sh + 31968;     // 32
    float* sMu  = sh + 32000;     // 64
    float* sMB  = sh + 32064;     // 64
    float* sTL  = sh + 32128;     // 32
    float* sRW  = sh + 32160;     // 32
    float* sSR  = sh + 32192;     // 32
    float* sLd  = sh + 32224;     // 32
    float* sSc  = sh + 32256;     // [0]=lw, [1]=logdet

    const int tid = threadIdx.x;
    const int j = blockIdx.x;
    unsigned gen = g_gen;

    // ---- constants into shared, once ----
    const float* Ag = tmat + j * 4096;
    for (int i = tid; i < 4096; i += NT) {
        float v = Ag[i];
        int r = i >> 6, c = i & 63;
        sA[i] = v;
        sAT[c * 64 + r] = v;
    }
    for (int i = tid; i < 2048; i += NT) {
        float v = obsm[i];
        int h = i >> 5, d = i & 31;
        sC[i] = v;
        sCT[d * 64 + h] = v;
    }
    if (tid < 64) sQ[tid] = expf(ltn[tid]);
    if (tid < 32) sR[tid] = expf(lon[tid]);
    if (tid >= 64 && tid < 96) {
        int k = tid - 64;
        float m = -1e30f;
        for (int c = 0; c < 32; ++c) m = fmaxf(m, tlogits[k * 32 + c]);
        float s = 0.f;
        for (int c = 0; c < 32; ++c) s += expf(tlogits[k * 32 + c] - m);
        sTL[k] = tlogits[k * 32 + j] - (m + logf(s));
    }
    if (tid >= 128 && tid < 192) sMu[tid - 128] = 0.f;
    for (int i = tid; i < 4096; i += NT) {
        int r = i >> 6, c = i & 63;
        sP[i] = (r == c) ? 1.f : 0.f;
    }
    __syncthreads();
    if (tid == 0) sSc[0] = sTL[0];
    __syncthreads();

    // t = 0 observation update (exports into buffer 1 for step 1)
    obs_update(data, sP, sC, sCT, sBW, sS, sR, sMu, sLd, sSc, tid, j, 1);

    for (int t = 1; t < TT; ++t) {
        const int b = t & 1;           // buffer exported at end of step t-1
        const int b2 = (t + 1) & 1;    // buffer to export at end of this step

        grid_barrier(gen);

        // P1: weights (warp 0) || prefetch g_mu -> sMUK (threads 32..255)
        if (tid < 32) {
            float lwk = sTL[tid] + __ldcg(&g_lw[b][tid]);
            float m = lwk;
#pragma unroll
            for (int o = 16; o; o >>= 1) m = fmaxf(m, __shfl_xor_sync(0xffffffffu, m, o));
            if (!(m > -9e29f)) {
                sRW[tid] = 1.f / 32.f;
                sSR[tid] = 0.1767766953f;
                if (tid == 0) sSc[0] = -1e30f;
            } else {
                float p = expf(lwk - m);
                float s = p;
#pragma unroll
                for (int o = 16; o; o >>= 1) s += __shfl_xor_sync(0xffffffffu, s, o);
                float rk = p / s;
                sRW[tid] = rk;
                sSR[tid] = sqrtf(rk);
                if (tid == 0) sSc[0] = m + logf(s);
            }
        } else {
            const float4* gm4 = reinterpret_cast<const float4*>(&g_mu[b][0][0]);
            float4* sm4 = reinterpret_cast<float4*>(sMUK);
#pragma unroll
            for (int q = 0; q < 3; ++q) {
                int idx = (tid - 32) + 224 * q;
                if (idx < 512) sm4[idx] = __ldcg(&gm4[idx]);
            }
        }
        __syncthreads();

        // P2: threads 0..63: mu_bar[h], then DMT column h (hidden under M-accum).
        //     threads 64..255: M = sum_k r_k P_k from the PACKED TRIANGLE, then
        //     mirror off-diagonal blocks into full sM.
        if (tid < 64) {
            float s = 0.f;
#pragma unroll 8
            for (int k = 0; k < 32; ++k)
                s = fmaf(sRW[k], sMUK[k * 64 + tid], s);
            sMB[tid] = s;
#pragma unroll 8
            for (int k = 0; k < 32; ++k)
                sDMT[k * 64 + tid] = sSR[k] * (sMUK[k * 64 + tid] - s);
        } else {
            const int base = tid - 64;          // 0..191
            const int it0 = base, it1 = base + 192, it2 = base + 384;
            const bool h2 = (it2 < 544);
            // decode (row, col, diag) per item — once per step
            int rw[3], cl[3]; bool dg[3];
            int its[3] = {it0, it1, it2};
#pragma unroll
            for (int q = 0; q < 3; ++q) {
                int item = its[q];
                if (item < 544) {
                    int bi = item >> 2, ii = item & 3;
                    int br = 0;
                    while ((br + 1) * (br + 2) / 2 <= bi) ++br;
                    int bc = bi - br * (br + 1) / 2;
                    rw[q] = br * 4 + ii; cl[q] = bc * 4; dg[q] = (br == bc);
                } else { rw[q] = 0; cl[q] = 0; dg[q] = true; }
            }
            float4 a0 = make_float4(0.f, 0.f, 0.f, 0.f), a1 = a0, a2 = a0;
            for (int k = 0; k < 32; ++k) {
                float rk = sRW[k];
                const float4* src = g_P[b][k];
                float4 v0 = __ldcg(&src[it0]);
                float4 v1 = __ldcg(&src[it1]);
                a0.x = fmaf(rk, v0.x, a0.x); a0.y = fmaf(rk, v0.y, a0.y);
                a0.z = fmaf(rk, v0.z, a0.z); a0.w = fmaf(rk, v0.w, a0.w);
                a1.x = fmaf(rk, v1.x, a1.x); a1.y = fmaf(rk, v1.y, a1.y);
                a1.z = fmaf(rk, v1.z, a1.z); a1.w = fmaf(rk, v1.w, a1.w);
                if (h2) {
                    float4 v2 = __ldcg(&src[it2]);
                    a2.x = fmaf(rk, v2.x, a2.x); a2.y = fmaf(rk, v2.y, a2.y);
                    a2.z = fmaf(rk, v2.z, a2.z); a2.w = fmaf(rk, v2.w, a2.w);
                }
            }
            float4 av[3] = {a0, a1, a2};
#pragma unroll
            for (int q = 0; q < 3; ++q) {
                if (its[q] < 544) {
                    int r = rw[q], c = cl[q];
                    *reinterpret_cast<float4*>(&sM[r * 64 + c]) = av[q];
                    if (!dg[q]) {   // mirror into upper triangle
                        sM[(c + 0) * 64 + r] = av[q].x;
                        sM[(c + 1) * 64 + r] = av[q].y;
                        sM[(c + 2) * 64 + r] = av[q].z;
                        sM[(c + 3) * 64 + r] = av[q].w;
                    }
                }
            }
        }
        __syncthreads();

        // P4: M += DMT^T DMT
        mmT<64, 64, 32, 4, 4, true, 2>(sDMT, 64, sDMT, 64, sM, 64, tid);
        __syncthreads();

        // P5: mu = A mu_bar (threads<64), then T = A M (all threads, same phase)
        if (tid < 64) {
            float s = 0.f;
#pragma unroll 8
            for (int g = 0; g < 64; ++g) s = fmaf(sA[tid * 64 + g], sMB[g], s);
            sMu[tid] = s;
        }
        mmT<64, 64, 64, 4, 4, false, 0>(sA, 64, sM, 64, sT, 64, tid);
        __syncthreads();

        // P6: P = T A^T + diag(Q), lower-triangle blocks + mirror (exactly symmetric)
        if (tid < 136) {
            int br = (int)((sqrtf(8.f * tid + 1.f) - 1.f) * 0.5f);
            while ((br + 1) * (br + 2) / 2 <= tid) ++br;
            while (br * (br + 1) / 2 > tid) --br;
            int bc = tid - br * (br + 1) / 2;

            float acc[4][4];
#pragma unroll
            for (int i = 0; i < 4; ++i)
#pragma unroll
                for (int jj = 0; jj < 4; ++jj) acc[i][jj] = 0.f;
#pragma unroll 16
            for (int h = 0; h < 64; ++h) {
                float a[4];
#pragma unroll
                for (int i = 0; i < 4; ++i) a[i] = sT[(br * 4 + i) * 64 + h];
                float4 bv = *reinterpret_cast<const float4*>(&sAT[h * 64 + bc * 4]);
#pragma unroll
                for (int i = 0; i < 4; ++i) {
                    acc[i][0] = fmaf(a[i], bv.x, acc[i][0]);
                    acc[i][1] = fmaf(a[i], bv.y, acc[i][1]);
                    acc[i][2] = fmaf(a[i], bv.z, acc[i][2]);
                    acc[i][3] = fmaf(a[i], bv.w, acc[i][3]);
                }
            }
            if (br > bc) {
#pragma unroll
                for (int i = 0; i < 4; ++i) {
                    int r = br * 4 + i;
                    float4 w = make_float4(acc[i][0], acc[i][1], acc[i][2], acc[i][3]);
                    *reinterpret_cast<float4*>(&sP[r * 64 + bc * 4]) = w;
#pragma unroll
                    for (int jj = 0; jj < 4; ++jj)
                        sP[(bc * 4 + jj) * 64 + r] = acc[i][jj];
                }
            } else {  // diagonal block: use lower part only, mirror within block
#pragma unroll
                for (int i = 0; i < 4; ++i) {
#pragma unroll
                    for (int jj = 0; jj <= i; ++jj) {
                        int r = br * 4 + i, c = bc * 4 + jj;
                        float v = acc[i][jj];
                        if (r == c) v += sQ[r];
                        sP[r * 64 + c] = v;
                        sP[c * 64 + r] = v;
                    }
                }
            }
        }
        __syncthreads();

        // P7..P11: observation update + fused triangle export into buffer b2
        obs_update(data + t * 32, sP, sC, sCT, sBW, sS, sR, sMu, sLd, sSc, tid, j, b2);
    }

    // final lw exported to buffer (TT)&1 == 0 at t = TT-1
    grid_barrier(gen);
    if (j == 0 && tid < 32) {
        float lwk = __ldcg(&g_lw[0][tid]);
        float m = lwk;
#pragma unroll
        for (int o = 16; o; o >>= 1) m = fmaxf(m, __shfl_xor_sync(0xffffffffu, m, o));
        float s = expf(lwk - m);
#pragma unroll
        for (int o = 16; o; o >>= 1) s += __shfl_xor_sync(0xffffffffu, s, o);
        if (tid == 0) out[0] = m + logf(s);
    }
}

extern "C" void kernel_launch(void* const* d_in, const int* in_sizes, int n_in,
                              void* d_out, int out_size)
{
    const float *data = nullptr, *tlogits = nullptr, *tmat = nullptr;
    const float *ltn = nullptr, *obsm = nullptr, *lon = nullptr;
    for (int i = 0; i < n_in; ++i) {
        switch (in_sizes[i]) {
            case TT * DOBS:        data    = (const float*)d_in[i]; break;
            case KC * KC:          tlogits = (const float*)d_in[i]; break;
            case KC * HD * HD:     tmat    = (const float*)d_in[i]; break;
            case HD:               ltn     = (const float*)d_in[i]; break;
            case HD * DOBS:        obsm    = (const float*)d_in[i]; break;
            case DOBS:             lon     = (const float*)d_in[i]; break;
        }
    }
    float* out = (float*)d_out;

    const int smem_bytes = 32264 * 4;   // ~129 KB dynamic shared
    cudaFuncSetAttribute(slds_kernel,
                         cudaFuncAttributeMaxDynamicSharedMemorySize, smem_bytes);
    slds_kernel<<<NCTA, NT, smem_bytes>>>(data, tlogits, tmat, ltn, obsm, lon, out);
}